// round 1
// baseline (speedup 1.0000x reference)
#include <cuda_runtime.h>
#include <math.h>

#define TPB 512
#define RPB 4
#define PB 8
#define LDW2 132
#define GSTRIDE 1664
#define W2T_FLOATS (128*LDW2)
#define WSOFF W2T_FLOATS
#define GOFF (W2T_FLOATS + 2080)
#define SMEM_FLOATS (GOFF + RPB*GSTRIDE)
#define SMEM_BYTES (SMEM_FLOATS*4)

__device__ __forceinline__ float sigf(float x){
    if (x >= 0.f) { return 1.f/(1.f+expf(-x)); }
    float e = expf(x);
    return e/(1.f+e);
}

// Evaluate SDF MLP for PB points whose depths are din[base..base+7].
// Results -> sout[base..]. All 512 threads must call (uniform barriers).
__device__ __forceinline__ void sdf_batch(
    const float* __restrict__ din, float* __restrict__ sout, int base,
    float ox,float oy,float oz,float dx,float dy,float dz,
    float w1x,float w1y,float w1z,float b1v,float b2v,float w3v,float b3v,
    float* gh1, float* gred, const float* W2T, int j,int warp,int lane)
{
    #pragma unroll
    for (int p=0;p<PB;p++){
        float dv = din[base+p];
        float px = ox+dv*dx, py = oy+dv*dy, pz = oz+dv*dz;
        float h = b1v + px*w1x + py*w1y + pz*w1z;
        gh1[p*128+j] = fmaxf(h,0.f);
    }
    __syncthreads();
    float acc[PB];
    #pragma unroll
    for (int p=0;p<PB;p++) acc[p]=b2v;
    const float4* wrow = (const float4*)(W2T + j*LDW2);
    #pragma unroll 4
    for (int k4=0;k4<32;k4++){
        float4 w4 = wrow[k4];
        #pragma unroll
        for (int p=0;p<PB;p++){
            float4 h4 = *(const float4*)(gh1 + p*128 + k4*4);
            acc[p] += w4.x*h4.x;
            acc[p] += w4.y*h4.y;
            acc[p] += w4.z*h4.z;
            acc[p] += w4.w*h4.w;
        }
    }
    #pragma unroll
    for (int p=0;p<PB;p++){
        float t = fmaxf(acc[p],0.f)*w3v;
        #pragma unroll
        for (int o=16;o;o>>=1) t += __shfl_down_sync(0xffffffffu,t,o);
        if (lane==0) gred[warp*PB+p] = t;
    }
    __syncthreads();
    if (j < PB){
        sout[base+j] = gred[j] + gred[8+j] + gred[16+j] + gred[24+j] + b3v;
    }
    __syncthreads();
}

__global__ void __launch_bounds__(TPB,2) neus_kernel(
    const float* __restrict__ rays_o, const float* __restrict__ rays_d,
    const float* __restrict__ W1, const float* __restrict__ b1,
    const float* __restrict__ W2, const float* __restrict__ b2,
    const float* __restrict__ W3, const float* __restrict__ b3,
    const float* __restrict__ R1, const float* __restrict__ r1,
    const float* __restrict__ R2, const float* __restrict__ r2,
    const float* __restrict__ s_val, float* __restrict__ out)
{
    extern __shared__ float sm[];
    float* W2T = sm;
    float* WS  = sm + WSOFF;
    float* W1s = WS;         // 384
    float* b1s = WS+384;     // 128
    float* b2s = WS+512;     // 128
    float* W3s = WS+640;     // 128
    float* R1s = WS+768;     // 768
    float* r1s = WS+1536;    // 128
    float* R2s = WS+1664;    // 384
    float* r2s = WS+2048;    // 3
    float* b3p = WS+2051;
    float* scp = WS+2052;

    const int tid = threadIdx.x;
    const int g = tid >> 7;
    const int j = tid & 127;
    const int warp = j >> 5, lane = j & 31;
    const int ray = blockIdx.x*RPB + g;

    // weight staging
    for (int idx=tid; idx<128*128; idx+=TPB){
        int k = idx >> 7, jj = idx & 127;
        W2T[jj*LDW2 + k] = W2[idx];
    }
    for (int idx=tid; idx<384; idx+=TPB) W1s[idx] = W1[idx];
    for (int idx=tid; idx<128; idx+=TPB){
        b1s[idx]=b1[idx]; b2s[idx]=b2[idx]; W3s[idx]=W3[idx]; r1s[idx]=r1[idx];
    }
    for (int idx=tid; idx<768; idx+=TPB) R1s[idx] = R1[idx];
    for (int idx=tid; idx<384; idx+=TPB) R2s[idx] = R2[idx];
    if (tid < 3) r2s[tid] = r2[tid];
    if (tid == 0){ b3p[0] = b3[0]; scp[0] = s_val[0]*64.0f; }

    float* G     = sm + GOFF + g*GSTRIDE;
    float* gd    = G;          // 128
    float* gsdf  = G+128;      // 128
    float* gh1   = G+256;      // 1024 (also radiance partials)
    float* gwb   = G+1280;     // 128  (alpha / w / visw)
    float* gcdf  = G+1408;     // 132  (cdf, later dmid)
    float* gdf   = G+1540;     // 16
    float* gsf   = G+1556;     // 16
    float* gred  = G+1572;     // 32
    float* gcon  = G+1604;     // 24
    float* gaux  = G+1628;     // 6

    if (j == 0){
        float ox=rays_o[ray*3+0], oy=rays_o[ray*3+1], oz=rays_o[ray*3+2];
        float ddx=rays_d[ray*3+0], ddy=rays_d[ray*3+1], ddz=rays_d[ray*3+2];
        float nrm = sqrtf(ddx*ddx+ddy*ddy+ddz*ddz);
        gaux[0]=ox; gaux[1]=oy; gaux[2]=oz;
        gaux[3]=ddx/nrm; gaux[4]=ddy/nrm; gaux[5]=ddz/nrm;
    }
    if (j < 64){
        float t = (j==63) ? 1.0f : (float)j * (1.0f/63.0f);
        gd[j] = 0.5f*(1.0f-t) + 4.0f*t;
    }
    __syncthreads();

    const float ox=gaux[0], oy=gaux[1], oz=gaux[2];
    const float dx=gaux[3], dy=gaux[4], dz=gaux[5];
    const float w1x=W1s[j], w1y=W1s[128+j], w1z=W1s[256+j];
    const float b1v=b1s[j], b2v=b2s[j], w3v=W3s[j], b3v=b3p[0];

    // ---- coarse SDF: 64 points, 8 batches ----
    for (int b=0;b<8;b++)
        sdf_batch(gd, gsdf, b*8, ox,oy,oz,dx,dy,dz, w1x,w1y,w1z,b1v,b2v,w3v,b3v,
                  gh1,gred,W2T,j,warp,lane);

    // ---- hierarchical upsampling: 4 iterations of 16 ----
    int n = 64;
    for (int it=0; it<4; it++){
        float s_i = 64.0f * (float)(1<<it);
        if (j < n-1){
            float psdf=gsdf[j], nsdf=gsdf[j+1], pz=gd[j], nz=gd[j+1];
            float dot = (nsdf-psdf)/(nz-pz+1e-5f);
            float pdot = 0.0f;
            if (j > 0){
                float ppsdf=gsdf[j-1], ppz=gd[j-1];
                pdot = (psdf-ppsdf)/(pz-ppz+1e-5f);
            }
            float dc = fminf(pdot,dot);
            dc = fminf(fmaxf(dc,-10.0f),0.0f);
            float mid = 0.5f*(psdf+nsdf), dist = nz-pz;
            float pe = mid - dc*dist*0.5f;
            float ne = mid + dc*dist*0.5f;
            float pc = sigf(pe*s_i), nc = sigf(ne*s_i);
            gwb[j] = (pc-nc+1e-5f)/(pc+1e-5f);
        }
        __syncthreads();
        if (j == 0){
            // alpha -> w(+1e-5), sum
            float T=1.0f, sum=0.0f;
            for (int k=0;k<n-1;k++){
                float a = gwb[k];
                float w = a*T + 1e-5f;
                T *= (1.0f - a + 1e-10f);
                gwb[k]=w; sum+=w;
            }
            gcdf[0]=0.0f;
            float c=0.0f;
            for (int k=0;k<n-1;k++){ c += gwb[k]/sum; gcdf[k+1]=c; }
            // inverse-cdf sampling of 16 new depths (two-pointer searchsorted)
            int pos = 0;
            for (int t16=0;t16<16;t16++){
                float u = (t16==15) ? 1.0f : (float)t16 * (1.0f/15.0f);
                while (pos < n && gcdf[pos] <= u) pos++;
                int below = pos-1; if (below > n-1) below = n-1; if (below < 0) below = 0;
                int above = (pos < n-1) ? pos : n-1;
                float cb=gcdf[below], ca=gcdf[above];
                float bb=gd[below],  ba=gd[above];
                float den = ca-cb; if (den < 1e-5f) den = 1.0f;
                float tt = (u-cb)/den;
                gdf[t16] = bb + tt*(ba-bb);
            }
        }
        __syncthreads();
        sdf_batch(gdf, gsf, 0, ox,oy,oz,dx,dy,dz, w1x,w1y,w1z,b1v,b2v,w3v,b3v,
                  gh1,gred,W2T,j,warp,lane);
        sdf_batch(gdf, gsf, 8, ox,oy,oz,dx,dy,dz, w1x,w1y,w1z,b1v,b2v,w3v,b3v,
                  gh1,gred,W2T,j,warp,lane);
        if (j == 0){
            // stable merge (old entries before equal fine entries), from the back
            int i=n-1, f=15, q=n+15;
            while (f >= 0){
                if (i >= 0 && gd[i] > gdf[f]){ gd[q]=gd[i]; gsdf[q]=gsdf[i]; i--; }
                else                         { gd[q]=gdf[f]; gsdf[q]=gsf[f];  f--; }
                q--;
            }
        }
        __syncthreads();
        n += 16;
    }

    // ---- final compositing (n == 128); reuse stored sdf (== reference recompute) ----
    const float s = scp[0];
    gcdf[j] = sigf(gsdf[j]*s);
    __syncthreads();
    if (j < 127){
        float a = (gcdf[j]-gcdf[j+1]+1e-5f)/(gcdf[j]+1e-5f);
        gwb[j] = fminf(fmaxf(a,0.0f),1.0f);
    }
    __syncthreads();
    if (j == 0){
        float T=1.0f;
        for (int k=0;k<127;k++){ float a=gwb[k]; gwb[k]=a*T; T*=(1.0f-a+1e-10f); }
    }
    if (j < 127) gcdf[j] = 0.5f*(gd[j]+gd[j+1]);  // dmid (thread0 also does this)
    __syncthreads();

    // ---- radiance net on 127 midpoints, batches of 8 ----
    const float r10=R1s[j],      r11=R1s[128+j], r12=R1s[256+j];
    const float r13=R1s[384+j],  r14=R1s[512+j], r15=R1s[640+j];
    const float rr1=r1s[j];
    const float rc0=R2s[3*j+0], rc1=R2s[3*j+1], rc2=R2s[3*j+2];
    float rgbacc = 0.0f;

    for (int b=0;b<16;b++){
        int base = b*8;
        #pragma unroll
        for (int p=0;p<PB;p++){
            int idx = base+p;
            float dm = gcdf[(idx<127)?idx:0];
            float px=ox+dm*dx, py=oy+dm*dy, pz=oz+dm*dz;
            float h = rr1 + px*r10 + py*r11 + pz*r12 + dx*r13 + dy*r14 + dz*r15;
            h = fmaxf(h,0.0f);
            float t0=h*rc0, t1=h*rc1, t2=h*rc2;
            #pragma unroll
            for (int o=16;o;o>>=1){
                t0 += __shfl_down_sync(0xffffffffu,t0,o);
                t1 += __shfl_down_sync(0xffffffffu,t1,o);
                t2 += __shfl_down_sync(0xffffffffu,t2,o);
            }
            if (lane==0){
                gh1[warp*24 + p*3+0]=t0;
                gh1[warp*24 + p*3+1]=t1;
                gh1[warp*24 + p*3+2]=t2;
            }
        }
        __syncthreads();
        if (j < 24){
            int p = j/3, c = j - p*3;
            int idx = base+p;
            float sum = gh1[j] + gh1[24+j] + gh1[48+j] + gh1[72+j] + r2s[c];
            float rad = sigf(sum);
            gcon[j] = (idx<127) ? gwb[idx]*rad : 0.0f;
        }
        __syncthreads();
        if (j < 3){
            float a=0.0f;
            #pragma unroll
            for (int p=0;p<8;p++) a += gcon[p*3+j];
            rgbacc += a;
        }
        __syncthreads();
    }

    if (j < 3) out[ray*5+j] = rgbacc;
    if (j == 0){
        float dep=0.0f, ac=0.0f;
        for (int k=0;k<127;k++){ dep += gwb[k]*gcdf[k]; ac += gwb[k]; }
        out[ray*5+3]=dep;
        out[ray*5+4]=ac;
    }
}

extern "C" void kernel_launch(void* const* d_in, const int* in_sizes, int n_in,
                              void* d_out, int out_size)
{
    const float* rays_o = (const float*)d_in[0];
    const float* rays_d = (const float*)d_in[1];
    const float* W1 = (const float*)d_in[2];
    const float* b1 = (const float*)d_in[3];
    const float* W2 = (const float*)d_in[4];
    const float* b2 = (const float*)d_in[5];
    const float* W3 = (const float*)d_in[6];
    const float* b3 = (const float*)d_in[7];
    const float* R1 = (const float*)d_in[8];
    const float* r1 = (const float*)d_in[9];
    const float* R2 = (const float*)d_in[10];
    const float* r2 = (const float*)d_in[11];
    const float* sv = (const float*)d_in[12];
    float* out = (float*)d_out;

    cudaFuncSetAttribute(neus_kernel, cudaFuncAttributeMaxDynamicSharedMemorySize, SMEM_BYTES);
    neus_kernel<<<8192/RPB, TPB, SMEM_BYTES>>>(rays_o,rays_d,W1,b1,W2,b2,W3,b3,R1,r1,R2,r2,sv,out);
}

// round 2
// speedup vs baseline: 1.2199x; 1.2199x over previous
#include <cuda_runtime.h>
#include <math.h>

#define TPB 512
#define LDW2 132
#define HSTR 132
#define GSTRIDE 2020
#define W2T_FLOATS (128*LDW2)
#define WSOFF W2T_FLOATS
#define GOFF (W2T_FLOATS + 2056)
#define SMEM_BYTES ((GOFF + 4*GSTRIDE)*4)

#define O_D    0
#define O_SDF  128
#define O_H1   256
#define O_WB   1312
#define O_CDF  1440
#define O_DF   1572
#define O_SF   1588
#define O_RED  1604
#define O_DM   1860
#define O_CON  1988
#define O_AUX  2012

typedef unsigned long long ull;

__device__ __forceinline__ ull fma2(ull a, ull b, ull c){
    ull d;
    asm("fma.rn.f32x2 %0, %1, %2, %3;" : "=l"(d) : "l"(a), "l"(b), "l"(c));
    return d;
}
__device__ __forceinline__ float lo32(ull v){ return __uint_as_float((unsigned)v); }
__device__ __forceinline__ float hi32(ull v){ return __uint_as_float((unsigned)(v>>32)); }

__device__ __forceinline__ float sigf(float x){
    if (x >= 0.f) { return 1.f/(1.f+expf(-x)); }
    float e = expf(x);
    return e/(1.f+e);
}

// One 8-point SDF MLP batch. All 512 threads participate (uniform barriers).
// Thread (j2,q,ph) computes hidden units {j2, j2+64} for points ph*4..ph*4+3
// of ray q. din/sout are offsets into ray q's G region.
__device__ __forceinline__ void sdf_batch(
    float* __restrict__ sm, int din_off, int base, int sout_off,
    int q, int j2, int ph, int warpid, int lane, int tid,
    float c0a,float c1a,float c0b,float c1b,
    float b2a,float b2b,float w3a,float w3b,float b3v,
    const float* __restrict__ W2T)
{
    float* G = sm + GOFF + q*GSTRIDE;
    const float* din = G + din_off;
    float* gh1 = G + O_H1;

    // layer 1
    #pragma unroll
    for (int pi=0; pi<4; pi++){
        int pt = ph*4 + pi;
        float dv = din[base + pt];
        gh1[pt*HSTR + j2]      = fmaxf(fmaf(dv, c1a, c0a), 0.f);
        gh1[pt*HSTR + j2 + 64] = fmaxf(fmaf(dv, c1b, c0b), 0.f);
    }
    __syncthreads();

    // layer 2: packed f32x2 (even-k lanes in .lo, odd-k in .hi)
    ull acc[8];
    #pragma unroll
    for (int pi=0; pi<4; pi++){
        acc[pi]   = (ull)__float_as_uint(b2a);
        acc[4+pi] = (ull)__float_as_uint(b2b);
    }
    const ulonglong2* wA = (const ulonglong2*)(W2T + j2*LDW2);
    const ulonglong2* wB = (const ulonglong2*)(W2T + (j2+64)*LDW2);
    const ulonglong2* hp0 = (const ulonglong2*)(gh1 + (ph*4+0)*HSTR);
    const ulonglong2* hp1 = (const ulonglong2*)(gh1 + (ph*4+1)*HSTR);
    const ulonglong2* hp2 = (const ulonglong2*)(gh1 + (ph*4+2)*HSTR);
    const ulonglong2* hp3 = (const ulonglong2*)(gh1 + (ph*4+3)*HSTR);
    #pragma unroll 4
    for (int k4=0; k4<32; k4++){
        ulonglong2 a2 = wA[k4];
        ulonglong2 b2 = wB[k4];
        ulonglong2 h;
        h = hp0[k4];
        acc[0]=fma2(a2.x,h.x,acc[0]); acc[0]=fma2(a2.y,h.y,acc[0]);
        acc[4]=fma2(b2.x,h.x,acc[4]); acc[4]=fma2(b2.y,h.y,acc[4]);
        h = hp1[k4];
        acc[1]=fma2(a2.x,h.x,acc[1]); acc[1]=fma2(a2.y,h.y,acc[1]);
        acc[5]=fma2(b2.x,h.x,acc[5]); acc[5]=fma2(b2.y,h.y,acc[5]);
        h = hp2[k4];
        acc[2]=fma2(a2.x,h.x,acc[2]); acc[2]=fma2(a2.y,h.y,acc[2]);
        acc[6]=fma2(b2.x,h.x,acc[6]); acc[6]=fma2(b2.y,h.y,acc[6]);
        h = hp3[k4];
        acc[3]=fma2(a2.x,h.x,acc[3]); acc[3]=fma2(a2.y,h.y,acc[3]);
        acc[7]=fma2(b2.x,h.x,acc[7]); acc[7]=fma2(b2.y,h.y,acc[7]);
    }

    // layer 3: relu, *W3, reduce over j2 within warp (strides 16,8), then
    // lanes 0..7 (j2%4==0; lane = q*2+ph) stage partials to smem.
    #pragma unroll
    for (int u=0; u<2; u++){
        float w3 = u ? w3b : w3a;
        #pragma unroll
        for (int pi=0; pi<4; pi++){
            ull a = acc[u*4+pi];
            float t = fmaxf(lo32(a)+hi32(a), 0.f) * w3;
            t += __shfl_down_sync(0xffffffffu, t, 16);
            t += __shfl_down_sync(0xffffffffu, t, 8);
            if (lane < 8){
                int pt = ph*4 + pi;
                G[O_RED + (pt*2+u)*16 + warpid] = t;
            }
        }
    }
    __syncthreads();
    if (tid < 32){
        int qq = tid & 3, pt = tid >> 2;
        const float* gr = sm + GOFF + qq*GSTRIDE + O_RED + pt*32;
        float s2 = b3v;
        #pragma unroll
        for (int w=0; w<32; w+=4){
            float4 v = *(const float4*)(gr + w);
            s2 += v.x + v.y + v.z + v.w;
        }
        (sm + GOFF + qq*GSTRIDE)[sout_off + base + pt] = s2;
    }
    __syncthreads();
}

__global__ void __launch_bounds__(TPB,2) neus_kernel(
    const float* __restrict__ rays_o, const float* __restrict__ rays_d,
    const float* __restrict__ W1, const float* __restrict__ b1,
    const float* __restrict__ W2, const float* __restrict__ b2,
    const float* __restrict__ W3, const float* __restrict__ b3,
    const float* __restrict__ R1, const float* __restrict__ r1,
    const float* __restrict__ R2, const float* __restrict__ r2,
    const float* __restrict__ s_val, float* __restrict__ out)
{
    extern __shared__ float sm[];
    float* W2T = sm;
    float* WS  = sm + WSOFF;
    float* W1s = WS;         // 384
    float* b1s = WS+384;     // 128
    float* b2s = WS+512;     // 128
    float* W3s = WS+640;     // 128
    float* R1s = WS+768;     // 768
    float* r1s = WS+1536;    // 128
    float* R2s = WS+1664;    // 384
    float* r2s = WS+2048;    // 3
    float* b3p = WS+2051;
    float* scp = WS+2052;

    const int tid = threadIdx.x;
    const int j2 = tid >> 3;          // 0..63
    const int q  = (tid >> 1) & 3;    // ray in block
    const int ph = tid & 1;           // point half
    const int warpid = tid >> 5;
    const int lane = tid & 31;
    const int e = j2*2 + ph;          // per-ray element index 0..127
    const int jA = j2, jB = j2 + 64;

    // weight staging
    for (int idx=tid; idx<128*128; idx+=TPB){
        int k = idx >> 7, jj = idx & 127;
        W2T[jj*LDW2 + k] = W2[idx];
    }
    for (int idx=tid; idx<384; idx+=TPB) W1s[idx] = W1[idx];
    for (int idx=tid; idx<128; idx+=TPB){
        b1s[idx]=b1[idx]; b2s[idx]=b2[idx]; W3s[idx]=W3[idx]; r1s[idx]=r1[idx];
    }
    for (int idx=tid; idx<768; idx+=TPB) R1s[idx] = R1[idx];
    for (int idx=tid; idx<384; idx+=TPB) R2s[idx] = R2[idx];
    if (tid < 3) r2s[tid] = r2[tid];
    if (tid == 0){ b3p[0] = b3[0]; scp[0] = s_val[0]*64.0f; }

    if (tid < 4){
        int ray = blockIdx.x*4 + tid;
        float* ga = sm + GOFF + tid*GSTRIDE + O_AUX;
        float ox=rays_o[ray*3+0], oy=rays_o[ray*3+1], oz=rays_o[ray*3+2];
        float ddx=rays_d[ray*3+0], ddy=rays_d[ray*3+1], ddz=rays_d[ray*3+2];
        float nrm = sqrtf(ddx*ddx+ddy*ddy+ddz*ddz);
        ga[0]=ox; ga[1]=oy; ga[2]=oz;
        ga[3]=ddx/nrm; ga[4]=ddy/nrm; ga[5]=ddz/nrm;
    }
    float* G = sm + GOFF + q*GSTRIDE;
    if (e < 64){
        float t = (e==63) ? 1.0f : (float)e * (1.0f/63.0f);
        G[O_D + e] = 0.5f*(1.0f-t) + 4.0f*t;
    }
    __syncthreads();

    const float ox=G[O_AUX+0], oy=G[O_AUX+1], oz=G[O_AUX+2];
    const float dx=G[O_AUX+3], dy=G[O_AUX+4], dz=G[O_AUX+5];

    const float c1a = dx*W1s[jA] + dy*W1s[128+jA] + dz*W1s[256+jA];
    const float c0a = b1s[jA] + ox*W1s[jA] + oy*W1s[128+jA] + oz*W1s[256+jA];
    const float c1b = dx*W1s[jB] + dy*W1s[128+jB] + dz*W1s[256+jB];
    const float c0b = b1s[jB] + ox*W1s[jB] + oy*W1s[128+jB] + oz*W1s[256+jB];
    const float b2a=b2s[jA], b2b=b2s[jB], w3a=W3s[jA], w3b=W3s[jB], b3v=b3p[0];

    // ---- coarse SDF: 64 points ----
    for (int b=0;b<8;b++)
        sdf_batch(sm, O_D, b*8, O_SDF, q,j2,ph,warpid,lane,tid,
                  c0a,c1a,c0b,c1b,b2a,b2b,w3a,w3b,b3v,W2T);

    // ---- hierarchical upsampling ----
    int n = 64;
    for (int it=0; it<4; it++){
        float s_i = 64.0f * (float)(1<<it);
        if (e < n-1){
            float psdf=G[O_SDF+e], nsdf=G[O_SDF+e+1], pz=G[O_D+e], nz=G[O_D+e+1];
            float dot = (nsdf-psdf)/(nz-pz+1e-5f);
            float pdot = 0.0f;
            if (e > 0){
                float ppsdf=G[O_SDF+e-1], ppz=G[O_D+e-1];
                pdot = (psdf-ppsdf)/(pz-ppz+1e-5f);
            }
            float dc = fminf(pdot,dot);
            dc = fminf(fmaxf(dc,-10.0f),0.0f);
            float mid = 0.5f*(psdf+nsdf), dist = nz-pz;
            float pe = mid - dc*dist*0.5f;
            float ne = mid + dc*dist*0.5f;
            float pc = sigf(pe*s_i), nc = sigf(ne*s_i);
            G[O_WB+e] = (pc-nc+1e-5f)/(pc+1e-5f);
        }
        __syncthreads();
        if (j2==0 && ph==0){
            // serial per-ray: cumprod, cdf, inverse-cdf sample of 16
            float T=1.0f, sum=0.0f;
            for (int k=0;k<n-1;k++){
                float a = G[O_WB+k];
                float w = a*T + 1e-5f;
                T *= (1.0f - a + 1e-10f);
                G[O_WB+k]=w; sum+=w;
            }
            float inv = 1.0f/sum;
            G[O_CDF+0]=0.0f;
            float c=0.0f;
            for (int k=0;k<n-1;k++){ c += G[O_WB+k]*inv; G[O_CDF+k+1]=c; }
            int pos = 0;
            for (int t16=0;t16<16;t16++){
                float u = (t16==15) ? 1.0f : (float)t16 * (1.0f/15.0f);
                while (pos < n && G[O_CDF+pos] <= u) pos++;
                int below = pos-1; if (below > n-1) below = n-1; if (below < 0) below = 0;
                int above = (pos < n-1) ? pos : n-1;
                float cb=G[O_CDF+below], ca=G[O_CDF+above];
                float bb=G[O_D+below],  ba=G[O_D+above];
                float den = ca-cb; if (den < 1e-5f) den = 1.0f;
                float tt = (u-cb)/den;
                G[O_DF+t16] = bb + tt*(ba-bb);
            }
        }
        __syncthreads();
        sdf_batch(sm, O_DF, 0, O_SF, q,j2,ph,warpid,lane,tid,
                  c0a,c1a,c0b,c1b,b2a,b2b,w3a,w3b,b3v,W2T);
        sdf_batch(sm, O_DF, 8, O_SF, q,j2,ph,warpid,lane,tid,
                  c0a,c1a,c0b,c1b,b2a,b2b,w3a,w3b,b3v,W2T);
        if (j2==0 && ph==0){
            // stable back-to-front merge (old entries before equal fine)
            int i=n-1, f=15, w=n+15;
            while (f >= 0){
                if (i >= 0 && G[O_D+i] > G[O_DF+f]){ G[O_D+w]=G[O_D+i]; G[O_SDF+w]=G[O_SDF+i]; i--; }
                else                               { G[O_D+w]=G[O_DF+f]; G[O_SDF+w]=G[O_SF+f]; f--; }
                w--;
            }
        }
        __syncthreads();
        n += 16;
    }

    // ---- final compositing (n==128, reuse stored sdf) ----
    const float s = scp[0];
    G[O_CDF + e] = sigf(G[O_SDF+e]*s);
    if (e < 127) G[O_DM + e] = 0.5f*(G[O_D+e] + G[O_D+e+1]);
    __syncthreads();
    if (e < 127){
        float a = (G[O_CDF+e]-G[O_CDF+e+1]+1e-5f)/(G[O_CDF+e]+1e-5f);
        G[O_WB+e] = fminf(fmaxf(a,0.0f),1.0f);
    }
    __syncthreads();
    if (j2==0 && ph==0){
        float T=1.0f, dep=0.0f, ac=0.0f;
        for (int k=0;k<127;k++){
            float a=G[O_WB+k];
            float w=a*T; T*=(1.0f-a+1e-10f);
            G[O_WB+k]=w;
            dep += w*G[O_DM+k]; ac += w;
        }
        int ray = blockIdx.x*4 + q;
        out[ray*5+3]=dep;
        out[ray*5+4]=ac;
    }
    __syncthreads();

    // ---- radiance net on 127 midpoints ----
    const float c1rA = dx*R1s[jA] + dy*R1s[128+jA] + dz*R1s[256+jA];
    const float c0rA = r1s[jA] + ox*R1s[jA] + oy*R1s[128+jA] + oz*R1s[256+jA]
                     + dx*R1s[384+jA] + dy*R1s[512+jA] + dz*R1s[640+jA];
    const float c1rB = dx*R1s[jB] + dy*R1s[128+jB] + dz*R1s[256+jB];
    const float c0rB = r1s[jB] + ox*R1s[jB] + oy*R1s[128+jB] + oz*R1s[256+jB]
                     + dx*R1s[384+jB] + dy*R1s[512+jB] + dz*R1s[640+jB];
    const float rcA0=R2s[3*jA+0], rcA1=R2s[3*jA+1], rcA2=R2s[3*jA+2];
    const float rcB0=R2s[3*jB+0], rcB1=R2s[3*jB+1], rcB2=R2s[3*jB+2];
    float rgb = 0.0f;  // meaningful for tid<12

    for (int b=0;b<16;b++){
        int base = b*8;
        #pragma unroll
        for (int pi=0; pi<4; pi++){
            int pt = ph*4 + pi;
            int idx = base + pt;
            float dm = G[O_DM + ((idx<127)?idx:0)];
            float hA = fmaxf(fmaf(dm, c1rA, c0rA), 0.f);
            float hB = fmaxf(fmaf(dm, c1rB, c0rB), 0.f);
            float t0 = hA*rcA0 + hB*rcB0;
            float t1 = hA*rcA1 + hB*rcB1;
            float t2 = hA*rcA2 + hB*rcB2;
            t0 += __shfl_down_sync(0xffffffffu, t0, 16);
            t0 += __shfl_down_sync(0xffffffffu, t0, 8);
            t1 += __shfl_down_sync(0xffffffffu, t1, 16);
            t1 += __shfl_down_sync(0xffffffffu, t1, 8);
            t2 += __shfl_down_sync(0xffffffffu, t2, 16);
            t2 += __shfl_down_sync(0xffffffffu, t2, 8);
            if (lane < 8){
                float* gp = G + O_H1;
                gp[(pt*3+0)*16 + warpid] = t0;
                gp[(pt*3+1)*16 + warpid] = t1;
                gp[(pt*3+2)*16 + warpid] = t2;
            }
        }
        __syncthreads();
        if (tid < 96){
            int qq = tid & 3, r = tid >> 2;      // r = pt*3+c, 0..23
            int p = r/3, c = r - p*3;
            const float* gp = sm + GOFF + qq*GSTRIDE + O_H1 + r*16;
            float su = 0.f;
            #pragma unroll
            for (int w=0; w<16; w+=4){
                float4 v = *(const float4*)(gp + w);
                su += v.x+v.y+v.z+v.w;
            }
            float rad = sigf(su + r2s[c]);
            int idx = base + p;
            float* Gq = sm + GOFF + qq*GSTRIDE;
            Gq[O_CON + r] = (idx<127) ? Gq[O_WB+idx]*rad : 0.0f;
        }
        __syncthreads();
        if (tid < 12){
            int qq = tid & 3, c = tid >> 2;
            const float* gc = sm + GOFF + qq*GSTRIDE + O_CON;
            float a = 0.f;
            #pragma unroll
            for (int p2=0; p2<8; p2++) a += gc[p2*3+c];
            rgb += a;
        }
        __syncthreads();
    }

    if (tid < 12){
        int qq = tid & 3, c = tid >> 2;
        out[(blockIdx.x*4+qq)*5 + c] = rgb;
    }
}

extern "C" void kernel_launch(void* const* d_in, const int* in_sizes, int n_in,
                              void* d_out, int out_size)
{
    const float* rays_o = (const float*)d_in[0];
    const float* rays_d = (const float*)d_in[1];
    const float* W1 = (const float*)d_in[2];
    const float* b1 = (const float*)d_in[3];
    const float* W2 = (const float*)d_in[4];
    const float* b2 = (const float*)d_in[5];
    const float* W3 = (const float*)d_in[6];
    const float* b3 = (const float*)d_in[7];
    const float* R1 = (const float*)d_in[8];
    const float* r1 = (const float*)d_in[9];
    const float* R2 = (const float*)d_in[10];
    const float* r2 = (const float*)d_in[11];
    const float* sv = (const float*)d_in[12];
    float* out = (float*)d_out;

    cudaFuncSetAttribute(neus_kernel, cudaFuncAttributeMaxDynamicSharedMemorySize, SMEM_BYTES);
    neus_kernel<<<8192/4, TPB, SMEM_BYTES>>>(rays_o,rays_d,W1,b1,W2,b2,W3,b3,R1,r1,R2,r2,sv,out);
}

// round 3
// speedup vs baseline: 1.6331x; 1.3387x over previous
#include <cuda_runtime.h>
#include <math.h>

#define TPB 512
#define RAYS 16
#define LDW2 132
#define HSTR 132
#define GSTRIDE 1760
#define W2T_FLOATS (128*LDW2)
#define WSOFF W2T_FLOATS
#define GOFF (W2T_FLOATS + 2056)
#define SMEM_BYTES ((GOFF + RAYS*GSTRIDE)*4)

#define O_D    0
#define O_SDF  128
#define O_H1   256
#define O_WB   1312
#define O_CDF  1440
#define O_DF   1572
#define O_SF   1588
#define O_DM   1604
#define O_AUX  1732

typedef unsigned long long ull;

__device__ __forceinline__ ull fma2(ull a, ull b, ull c){
    ull d;
    asm("fma.rn.f32x2 %0, %1, %2, %3;" : "=l"(d) : "l"(a), "l"(b), "l"(c));
    return d;
}
__device__ __forceinline__ float lo32(ull v){ return __uint_as_float((unsigned)v); }
__device__ __forceinline__ float hi32(ull v){ return __uint_as_float((unsigned)(v>>32)); }

__device__ __forceinline__ float sigf(float x){
    if (x >= 0.f) { return 1.f/(1.f+expf(-x)); }
    float e = expf(x);
    return e/(1.f+e);
}

// One 8-point SDF MLP batch for THIS warp's ray. Warp-private: only __syncwarp.
// Lane owns units {lane, lane+32, lane+64, lane+96}; each thread does all 8 pts.
__device__ __forceinline__ void sdf_batch(
    float* __restrict__ G, const float* __restrict__ W2T,
    int din_off, int base, int sout_off, int lane,
    const float* c0, const float* c1, const float* b2v, const float* w3v,
    float b3v)
{
    float* gh1 = G + O_H1;
    // layer 1: h[pt][unit]
    #pragma unroll
    for (int pt=0; pt<8; pt++){
        float dv = G[din_off + base + pt];
        #pragma unroll
        for (int u=0; u<4; u++){
            gh1[pt*HSTR + lane + 32*u] = fmaxf(fmaf(dv, c1[u], c0[u]), 0.f);
        }
    }
    __syncwarp();

    // layer 2: U4 x P8 register block, packed f32x2
    ull acc[4][8];
    #pragma unroll
    for (int u=0; u<4; u++)
        #pragma unroll
        for (int p=0; p<8; p++)
            acc[u][p] = (ull)__float_as_uint(b2v[u]);

    const ulonglong2* w0 = (const ulonglong2*)(W2T + (lane      )*LDW2);
    const ulonglong2* w1 = (const ulonglong2*)(W2T + (lane + 32 )*LDW2);
    const ulonglong2* w2r= (const ulonglong2*)(W2T + (lane + 64 )*LDW2);
    const ulonglong2* w3r= (const ulonglong2*)(W2T + (lane + 96 )*LDW2);

    #pragma unroll 4
    for (int k4=0; k4<32; k4++){
        ulonglong2 wv[4];
        wv[0]=w0[k4]; wv[1]=w1[k4]; wv[2]=w2r[k4]; wv[3]=w3r[k4];
        #pragma unroll
        for (int hh=0; hh<2; hh++){
            ulonglong2 hv[4];
            #pragma unroll
            for (int i=0;i<4;i++)
                hv[i] = *(const ulonglong2*)(gh1 + (hh*4+i)*HSTR + k4*4);
            #pragma unroll
            for (int u=0; u<4; u++){
                #pragma unroll
                for (int i=0; i<4; i++){
                    int p = hh*4 + i;
                    acc[u][p] = fma2(wv[u].x, hv[i].x, acc[u][p]);
                    acc[u][p] = fma2(wv[u].y, hv[i].y, acc[u][p]);
                }
            }
        }
    }

    // layer 3: relu, *W3, warp-reduce, lane0 writes sdf
    #pragma unroll
    for (int pt=0; pt<8; pt++){
        float t = 0.f;
        #pragma unroll
        for (int u=0; u<4; u++){
            float f = lo32(acc[u][pt]) + hi32(acc[u][pt]);
            t += fmaxf(f, 0.f) * w3v[u];
        }
        #pragma unroll
        for (int o=16;o;o>>=1) t += __shfl_down_sync(0xffffffffu, t, o);
        if (lane == 0) G[sout_off + base + pt] = t + b3v;
    }
    __syncwarp();
}

__global__ void __launch_bounds__(TPB,1) neus_kernel(
    const float* __restrict__ rays_o, const float* __restrict__ rays_d,
    const float* __restrict__ W1, const float* __restrict__ b1,
    const float* __restrict__ W2, const float* __restrict__ b2,
    const float* __restrict__ W3, const float* __restrict__ b3,
    const float* __restrict__ R1, const float* __restrict__ r1,
    const float* __restrict__ R2, const float* __restrict__ r2,
    const float* __restrict__ s_val, float* __restrict__ out)
{
    extern __shared__ float sm[];
    float* W2T = sm;
    float* WS  = sm + WSOFF;
    float* W1s = WS;         // 384
    float* b1s = WS+384;     // 128
    float* b2s = WS+512;     // 128
    float* W3s = WS+640;     // 128
    float* R1s = WS+768;     // 768
    float* r1s = WS+1536;    // 128
    float* R2s = WS+1664;    // 384
    float* r2s = WS+2048;    // 3
    float* b3p = WS+2051;
    float* scp = WS+2052;

    const int tid  = threadIdx.x;
    const int w    = tid >> 5;     // warp = ray-in-block
    const int lane = tid & 31;
    const int ray  = blockIdx.x*RAYS + w;

    // ---- weight staging (block-wide, once) ----
    for (int idx=tid; idx<128*128; idx+=TPB){
        int k = idx >> 7, jj = idx & 127;
        W2T[jj*LDW2 + k] = W2[idx];
    }
    for (int idx=tid; idx<384; idx+=TPB) W1s[idx] = W1[idx];
    for (int idx=tid; idx<128; idx+=TPB){
        b1s[idx]=b1[idx]; b2s[idx]=b2[idx]; W3s[idx]=W3[idx]; r1s[idx]=r1[idx];
    }
    for (int idx=tid; idx<768; idx+=TPB) R1s[idx] = R1[idx];
    for (int idx=tid; idx<384; idx+=TPB) R2s[idx] = R2[idx];
    if (tid < 3) r2s[tid] = r2[tid];
    if (tid == 0){ b3p[0] = b3[0]; scp[0] = s_val[0]*64.0f; }
    __syncthreads();

    float* G = sm + GOFF + w*GSTRIDE;

    if (lane == 0){
        float ox=rays_o[ray*3+0], oy=rays_o[ray*3+1], oz=rays_o[ray*3+2];
        float ddx=rays_d[ray*3+0], ddy=rays_d[ray*3+1], ddz=rays_d[ray*3+2];
        float nrm = sqrtf(ddx*ddx+ddy*ddy+ddz*ddz);
        G[O_AUX+0]=ox; G[O_AUX+1]=oy; G[O_AUX+2]=oz;
        G[O_AUX+3]=ddx/nrm; G[O_AUX+4]=ddy/nrm; G[O_AUX+5]=ddz/nrm;
    }
    #pragma unroll
    for (int e=lane; e<64; e+=32){
        float t = (e==63) ? 1.0f : (float)e * (1.0f/63.0f);
        G[O_D + e] = 0.5f*(1.0f-t) + 4.0f*t;
    }
    __syncwarp();

    const float ox=G[O_AUX+0], oy=G[O_AUX+1], oz=G[O_AUX+2];
    const float dx=G[O_AUX+3], dy=G[O_AUX+4], dz=G[O_AUX+5];

    float c0[4], c1[4], b2v[4], w3v[4];
    #pragma unroll
    for (int u=0; u<4; u++){
        int j = lane + 32*u;
        c1[u] = dx*W1s[j] + dy*W1s[128+j] + dz*W1s[256+j];
        c0[u] = b1s[j] + ox*W1s[j] + oy*W1s[128+j] + oz*W1s[256+j];
        b2v[u]= b2s[j];
        w3v[u]= W3s[j];
    }
    const float b3v = b3p[0];

    // ---- coarse: 64 points ----
    for (int b=0;b<8;b++)
        sdf_batch(G, W2T, O_D, b*8, O_SDF, lane, c0,c1,b2v,w3v,b3v);

    // ---- hierarchical upsampling ----
    int n = 64;
    for (int it=0; it<4; it++){
        float s_i = 64.0f * (float)(1<<it);
        for (int e=lane; e<n-1; e+=32){
            float psdf=G[O_SDF+e], nsdf=G[O_SDF+e+1], pz=G[O_D+e], nz=G[O_D+e+1];
            float dot = (nsdf-psdf)/(nz-pz+1e-5f);
            float pdot = 0.0f;
            if (e > 0){
                float ppsdf=G[O_SDF+e-1], ppz=G[O_D+e-1];
                pdot = (psdf-ppsdf)/(pz-ppz+1e-5f);
            }
            float dc = fminf(pdot,dot);
            dc = fminf(fmaxf(dc,-10.0f),0.0f);
            float mid = 0.5f*(psdf+nsdf), dist = nz-pz;
            float pe = mid - dc*dist*0.5f;
            float ne = mid + dc*dist*0.5f;
            float pc = sigf(pe*s_i), nc = sigf(ne*s_i);
            G[O_WB+e] = (pc-nc+1e-5f)/(pc+1e-5f);
        }
        __syncwarp();
        if (lane == 0){
            float T=1.0f, sum=0.0f;
            for (int k=0;k<n-1;k++){
                float a = G[O_WB+k];
                float wv = a*T + 1e-5f;
                T *= (1.0f - a + 1e-10f);
                G[O_WB+k]=wv; sum+=wv;
            }
            float inv = 1.0f/sum;
            G[O_CDF+0]=0.0f;
            float c=0.0f;
            for (int k=0;k<n-1;k++){ c += G[O_WB+k]*inv; G[O_CDF+k+1]=c; }
            int pos = 0;
            for (int t16=0;t16<16;t16++){
                float u = (t16==15) ? 1.0f : (float)t16 * (1.0f/15.0f);
                while (pos < n && G[O_CDF+pos] <= u) pos++;
                int below = pos-1; if (below > n-1) below = n-1; if (below < 0) below = 0;
                int above = (pos < n-1) ? pos : n-1;
                float cb=G[O_CDF+below], ca=G[O_CDF+above];
                float bb=G[O_D+below],  ba=G[O_D+above];
                float den = ca-cb; if (den < 1e-5f) den = 1.0f;
                float tt = (u-cb)/den;
                G[O_DF+t16] = bb + tt*(ba-bb);
            }
        }
        __syncwarp();
        sdf_batch(G, W2T, O_DF, 0, O_SF, lane, c0,c1,b2v,w3v,b3v);
        sdf_batch(G, W2T, O_DF, 8, O_SF, lane, c0,c1,b2v,w3v,b3v);
        if (lane == 0){
            // stable back-to-front merge (old entries before equal fine)
            int i=n-1, f=15, q=n+15;
            while (f >= 0){
                if (i >= 0 && G[O_D+i] > G[O_DF+f]){ G[O_D+q]=G[O_D+i]; G[O_SDF+q]=G[O_SDF+i]; i--; }
                else                               { G[O_D+q]=G[O_DF+f]; G[O_SDF+q]=G[O_SF+f]; f--; }
                q--;
            }
        }
        __syncwarp();
        n += 16;
    }

    // ---- final compositing (n==128, reuse stored sdf) ----
    const float s = scp[0];
    #pragma unroll
    for (int e=lane; e<128; e+=32) G[O_CDF+e] = sigf(G[O_SDF+e]*s);
    #pragma unroll
    for (int e=lane; e<127; e+=32) G[O_DM+e] = 0.5f*(G[O_D+e]+G[O_D+e+1]);
    __syncwarp();
    #pragma unroll
    for (int e=lane; e<127; e+=32){
        float a = (G[O_CDF+e]-G[O_CDF+e+1]+1e-5f)/(G[O_CDF+e]+1e-5f);
        G[O_WB+e] = fminf(fmaxf(a,0.0f),1.0f);
    }
    __syncwarp();
    if (lane == 0){
        float T=1.0f, dep=0.0f, ac=0.0f;
        for (int k=0;k<127;k++){
            float a=G[O_WB+k];
            float wv=a*T; T*=(1.0f-a+1e-10f);
            G[O_WB+k]=wv;
            dep += wv*G[O_DM+k]; ac += wv;
        }
        out[ray*5+3]=dep;
        out[ray*5+4]=ac;
    }
    __syncwarp();

    // ---- radiance net on 127 midpoints (warp-private) ----
    float c0r[4], c1r[4], rc0[4], rc1[4], rc2[4];
    #pragma unroll
    for (int u=0; u<4; u++){
        int j = lane + 32*u;
        c1r[u] = dx*R1s[j] + dy*R1s[128+j] + dz*R1s[256+j];
        c0r[u] = r1s[j] + ox*R1s[j] + oy*R1s[128+j] + oz*R1s[256+j]
               + dx*R1s[384+j] + dy*R1s[512+j] + dz*R1s[640+j];
        rc0[u]=R2s[3*j+0]; rc1[u]=R2s[3*j+1]; rc2[u]=R2s[3*j+2];
    }
    const float r2c0=r2s[0], r2c1=r2s[1], r2c2=r2s[2];
    float rgb0=0.f, rgb1=0.f, rgb2=0.f;

    for (int pt=0; pt<127; pt++){
        float dm = G[O_DM+pt];
        float t0=0.f, t1=0.f, t2=0.f;
        #pragma unroll
        for (int u=0; u<4; u++){
            float h = fmaxf(fmaf(dm, c1r[u], c0r[u]), 0.f);
            t0 = fmaf(h, rc0[u], t0);
            t1 = fmaf(h, rc1[u], t1);
            t2 = fmaf(h, rc2[u], t2);
        }
        #pragma unroll
        for (int o=16;o;o>>=1){
            t0 += __shfl_down_sync(0xffffffffu, t0, o);
            t1 += __shfl_down_sync(0xffffffffu, t1, o);
            t2 += __shfl_down_sync(0xffffffffu, t2, o);
        }
        if (lane == 0){
            float wv = G[O_WB+pt];
            rgb0 = fmaf(wv, sigf(t0+r2c0), rgb0);
            rgb1 = fmaf(wv, sigf(t1+r2c1), rgb1);
            rgb2 = fmaf(wv, sigf(t2+r2c2), rgb2);
        }
    }
    if (lane == 0){
        out[ray*5+0]=rgb0;
        out[ray*5+1]=rgb1;
        out[ray*5+2]=rgb2;
    }
}

extern "C" void kernel_launch(void* const* d_in, const int* in_sizes, int n_in,
                              void* d_out, int out_size)
{
    const float* rays_o = (const float*)d_in[0];
    const float* rays_d = (const float*)d_in[1];
    const float* W1 = (const float*)d_in[2];
    const float* b1 = (const float*)d_in[3];
    const float* W2 = (const float*)d_in[4];
    const float* b2 = (const float*)d_in[5];
    const float* W3 = (const float*)d_in[6];
    const float* b3 = (const float*)d_in[7];
    const float* R1 = (const float*)d_in[8];
    const float* r1 = (const float*)d_in[9];
    const float* R2 = (const float*)d_in[10];
    const float* r2 = (const float*)d_in[11];
    const float* sv = (const float*)d_in[12];
    float* out = (float*)d_out;

    cudaFuncSetAttribute(neus_kernel, cudaFuncAttributeMaxDynamicSharedMemorySize, SMEM_BYTES);
    neus_kernel<<<8192/RAYS, TPB, SMEM_BYTES>>>(rays_o,rays_d,W1,b1,W2,b2,W3,b3,R1,r1,R2,r2,sv,out);
}

// round 4
// speedup vs baseline: 1.6333x; 1.0001x over previous
#include <cuda_runtime.h>
#include <math.h>

#define TPB 512
#define RAYS 16
#define LDW2 132
#define HSTR 132
#define GSTRIDE 1760
#define W2T_FLOATS (128*LDW2)
#define WSOFF W2T_FLOATS
#define GOFF (W2T_FLOATS + 2056)
#define SMEM_BYTES ((GOFF + RAYS*GSTRIDE)*4)

#define O_D    0
#define O_SDF  128
#define O_H1   256
#define O_WB   1312
#define O_CDF  1440
#define O_DF   1572
#define O_SF   1588
#define O_DM   1604
#define O_AUX  1732

typedef unsigned long long ull;

__device__ __forceinline__ ull fma2(ull a, ull b, ull c){
    ull d;
    asm("fma.rn.f32x2 %0, %1, %2, %3;" : "=l"(d) : "l"(a), "l"(b), "l"(c));
    return d;
}
__device__ __forceinline__ float lo32(ull v){ return __uint_as_float((unsigned)v); }
__device__ __forceinline__ float hi32(ull v){ return __uint_as_float((unsigned)(v>>32)); }

__device__ __forceinline__ float sigf(float x){
    if (x >= 0.f) { return 1.f/(1.f+expf(-x)); }
    float e = expf(x);
    return e/(1.f+e);
}

// One 8-point SDF MLP batch for THIS warp's ray. Warp-private: only __syncwarp.
// Lane owns units {lane, lane+32, lane+64, lane+96}; each thread does all 8 pts.
__device__ __forceinline__ void sdf_batch(
    float* __restrict__ G, const float* __restrict__ W2T,
    int din_off, int base, int sout_off, int lane,
    const float* c0, const float* c1, const float* b2v, const float* w3v,
    float b3v)
{
    float* gh1 = G + O_H1;
    // layer 1: h[pt][unit]
    #pragma unroll
    for (int pt=0; pt<8; pt++){
        float dv = G[din_off + base + pt];
        #pragma unroll
        for (int u=0; u<4; u++){
            gh1[pt*HSTR + lane + 32*u] = fmaxf(fmaf(dv, c1[u], c0[u]), 0.f);
        }
    }
    __syncwarp();

    // layer 2: U4 x P8 register block, packed f32x2
    ull acc[4][8];
    #pragma unroll
    for (int u=0; u<4; u++)
        #pragma unroll
        for (int p=0; p<8; p++)
            acc[u][p] = (ull)__float_as_uint(b2v[u]);

    const ulonglong2* w0 = (const ulonglong2*)(W2T + (lane      )*LDW2);
    const ulonglong2* w1 = (const ulonglong2*)(W2T + (lane + 32 )*LDW2);
    const ulonglong2* w2r= (const ulonglong2*)(W2T + (lane + 64 )*LDW2);
    const ulonglong2* w3r= (const ulonglong2*)(W2T + (lane + 96 )*LDW2);

    #pragma unroll 4
    for (int k4=0; k4<32; k4++){
        ulonglong2 wv[4];
        wv[0]=w0[k4]; wv[1]=w1[k4]; wv[2]=w2r[k4]; wv[3]=w3r[k4];
        #pragma unroll
        for (int hh=0; hh<2; hh++){
            ulonglong2 hv[4];
            #pragma unroll
            for (int i=0;i<4;i++)
                hv[i] = *(const ulonglong2*)(gh1 + (hh*4+i)*HSTR + k4*4);
            #pragma unroll
            for (int u=0; u<4; u++){
                #pragma unroll
                for (int i=0; i<4; i++){
                    int p = hh*4 + i;
                    acc[u][p] = fma2(wv[u].x, hv[i].x, acc[u][p]);
                    acc[u][p] = fma2(wv[u].y, hv[i].y, acc[u][p]);
                }
            }
        }
    }

    // layer 3: relu, *W3, warp-reduce, lane0 writes sdf
    #pragma unroll
    for (int pt=0; pt<8; pt++){
        float t = 0.f;
        #pragma unroll
        for (int u=0; u<4; u++){
            float f = lo32(acc[u][pt]) + hi32(acc[u][pt]);
            t += fmaxf(f, 0.f) * w3v[u];
        }
        #pragma unroll
        for (int o=16;o;o>>=1) t += __shfl_down_sync(0xffffffffu, t, o);
        if (lane == 0) G[sout_off + base + pt] = t + b3v;
    }
    __syncwarp();
}

__global__ void __launch_bounds__(TPB,1) neus_kernel(
    const float* __restrict__ rays_o, const float* __restrict__ rays_d,
    const float* __restrict__ W1, const float* __restrict__ b1,
    const float* __restrict__ W2, const float* __restrict__ b2,
    const float* __restrict__ W3, const float* __restrict__ b3,
    const float* __restrict__ R1, const float* __restrict__ r1,
    const float* __restrict__ R2, const float* __restrict__ r2,
    const float* __restrict__ s_val, float* __restrict__ out)
{
    extern __shared__ float sm[];
    float* W2T = sm;
    float* WS  = sm + WSOFF;
    float* W1s = WS;         // 384
    float* b1s = WS+384;     // 128
    float* b2s = WS+512;     // 128
    float* W3s = WS+640;     // 128
    float* R1s = WS+768;     // 768
    float* r1s = WS+1536;    // 128
    float* R2s = WS+1664;    // 384
    float* r2s = WS+2048;    // 3
    float* b3p = WS+2051;
    float* scp = WS+2052;

    const int tid  = threadIdx.x;
    const int w    = tid >> 5;     // warp = ray-in-block
    const int lane = tid & 31;
    const int ray  = blockIdx.x*RAYS + w;

    // ---- weight staging (block-wide, once) ----
    for (int idx=tid; idx<128*128; idx+=TPB){
        int k = idx >> 7, jj = idx & 127;
        W2T[jj*LDW2 + k] = W2[idx];
    }
    for (int idx=tid; idx<384; idx+=TPB) W1s[idx] = W1[idx];
    for (int idx=tid; idx<128; idx+=TPB){
        b1s[idx]=b1[idx]; b2s[idx]=b2[idx]; W3s[idx]=W3[idx]; r1s[idx]=r1[idx];
    }
    for (int idx=tid; idx<768; idx+=TPB) R1s[idx] = R1[idx];
    for (int idx=tid; idx<384; idx+=TPB) R2s[idx] = R2[idx];
    if (tid < 3) r2s[tid] = r2[tid];
    if (tid == 0){ b3p[0] = b3[0]; scp[0] = s_val[0]*64.0f; }
    __syncthreads();

    float* G = sm + GOFF + w*GSTRIDE;

    if (lane == 0){
        float ox=rays_o[ray*3+0], oy=rays_o[ray*3+1], oz=rays_o[ray*3+2];
        float ddx=rays_d[ray*3+0], ddy=rays_d[ray*3+1], ddz=rays_d[ray*3+2];
        float nrm = sqrtf(ddx*ddx+ddy*ddy+ddz*ddz);
        G[O_AUX+0]=ox; G[O_AUX+1]=oy; G[O_AUX+2]=oz;
        G[O_AUX+3]=ddx/nrm; G[O_AUX+4]=ddy/nrm; G[O_AUX+5]=ddz/nrm;
    }
    #pragma unroll
    for (int e=lane; e<64; e+=32){
        float t = (e==63) ? 1.0f : (float)e * (1.0f/63.0f);
        G[O_D + e] = 0.5f*(1.0f-t) + 4.0f*t;
    }
    __syncwarp();

    const float ox=G[O_AUX+0], oy=G[O_AUX+1], oz=G[O_AUX+2];
    const float dx=G[O_AUX+3], dy=G[O_AUX+4], dz=G[O_AUX+5];

    float c0[4], c1[4], b2v[4], w3v[4];
    #pragma unroll
    for (int u=0; u<4; u++){
        int j = lane + 32*u;
        c1[u] = dx*W1s[j] + dy*W1s[128+j] + dz*W1s[256+j];
        c0[u] = b1s[j] + ox*W1s[j] + oy*W1s[128+j] + oz*W1s[256+j];
        b2v[u]= b2s[j];
        w3v[u]= W3s[j];
    }
    const float b3v = b3p[0];

    // ---- coarse: 64 points ----
    for (int b=0;b<8;b++)
        sdf_batch(G, W2T, O_D, b*8, O_SDF, lane, c0,c1,b2v,w3v,b3v);

    // ---- hierarchical upsampling ----
    int n = 64;
    for (int it=0; it<4; it++){
        float s_i = 64.0f * (float)(1<<it);
        for (int e=lane; e<n-1; e+=32){
            float psdf=G[O_SDF+e], nsdf=G[O_SDF+e+1], pz=G[O_D+e], nz=G[O_D+e+1];
            float dot = (nsdf-psdf)/(nz-pz+1e-5f);
            float pdot = 0.0f;
            if (e > 0){
                float ppsdf=G[O_SDF+e-1], ppz=G[O_D+e-1];
                pdot = (psdf-ppsdf)/(pz-ppz+1e-5f);
            }
            float dc = fminf(pdot,dot);
            dc = fminf(fmaxf(dc,-10.0f),0.0f);
            float mid = 0.5f*(psdf+nsdf), dist = nz-pz;
            float pe = mid - dc*dist*0.5f;
            float ne = mid + dc*dist*0.5f;
            float pc = sigf(pe*s_i), nc = sigf(ne*s_i);
            G[O_WB+e] = (pc-nc+1e-5f)/(pc+1e-5f);
        }
        __syncwarp();
        if (lane == 0){
            float T=1.0f, sum=0.0f;
            for (int k=0;k<n-1;k++){
                float a = G[O_WB+k];
                float wv = a*T + 1e-5f;
                T *= (1.0f - a + 1e-10f);
                G[O_WB+k]=wv; sum+=wv;
            }
            float inv = 1.0f/sum;
            G[O_CDF+0]=0.0f;
            float c=0.0f;
            for (int k=0;k<n-1;k++){ c += G[O_WB+k]*inv; G[O_CDF+k+1]=c; }
            int pos = 0;
            for (int t16=0;t16<16;t16++){
                float u = (t16==15) ? 1.0f : (float)t16 * (1.0f/15.0f);
                while (pos < n && G[O_CDF+pos] <= u) pos++;
                int below = pos-1; if (below > n-1) below = n-1; if (below < 0) below = 0;
                int above = (pos < n-1) ? pos : n-1;
                float cb=G[O_CDF+below], ca=G[O_CDF+above];
                float bb=G[O_D+below],  ba=G[O_D+above];
                float den = ca-cb; if (den < 1e-5f) den = 1.0f;
                float tt = (u-cb)/den;
                G[O_DF+t16] = bb + tt*(ba-bb);
            }
        }
        __syncwarp();
        sdf_batch(G, W2T, O_DF, 0, O_SF, lane, c0,c1,b2v,w3v,b3v);
        sdf_batch(G, W2T, O_DF, 8, O_SF, lane, c0,c1,b2v,w3v,b3v);
        if (lane == 0){
            // stable back-to-front merge (old entries before equal fine)
            int i=n-1, f=15, q=n+15;
            while (f >= 0){
                if (i >= 0 && G[O_D+i] > G[O_DF+f]){ G[O_D+q]=G[O_D+i]; G[O_SDF+q]=G[O_SDF+i]; i--; }
                else                               { G[O_D+q]=G[O_DF+f]; G[O_SDF+q]=G[O_SF+f]; f--; }
                q--;
            }
        }
        __syncwarp();
        n += 16;
    }

    // ---- final compositing (n==128, reuse stored sdf) ----
    const float s = scp[0];
    #pragma unroll
    for (int e=lane; e<128; e+=32) G[O_CDF+e] = sigf(G[O_SDF+e]*s);
    #pragma unroll
    for (int e=lane; e<127; e+=32) G[O_DM+e] = 0.5f*(G[O_D+e]+G[O_D+e+1]);
    __syncwarp();
    #pragma unroll
    for (int e=lane; e<127; e+=32){
        float a = (G[O_CDF+e]-G[O_CDF+e+1]+1e-5f)/(G[O_CDF+e]+1e-5f);
        G[O_WB+e] = fminf(fmaxf(a,0.0f),1.0f);
    }
    __syncwarp();
    if (lane == 0){
        float T=1.0f, dep=0.0f, ac=0.0f;
        for (int k=0;k<127;k++){
            float a=G[O_WB+k];
            float wv=a*T; T*=(1.0f-a+1e-10f);
            G[O_WB+k]=wv;
            dep += wv*G[O_DM+k]; ac += wv;
        }
        out[ray*5+3]=dep;
        out[ray*5+4]=ac;
    }
    __syncwarp();

    // ---- radiance net on 127 midpoints (warp-private) ----
    float c0r[4], c1r[4], rc0[4], rc1[4], rc2[4];
    #pragma unroll
    for (int u=0; u<4; u++){
        int j = lane + 32*u;
        c1r[u] = dx*R1s[j] + dy*R1s[128+j] + dz*R1s[256+j];
        c0r[u] = r1s[j] + ox*R1s[j] + oy*R1s[128+j] + oz*R1s[256+j]
               + dx*R1s[384+j] + dy*R1s[512+j] + dz*R1s[640+j];
        rc0[u]=R2s[3*j+0]; rc1[u]=R2s[3*j+1]; rc2[u]=R2s[3*j+2];
    }
    const float r2c0=r2s[0], r2c1=r2s[1], r2c2=r2s[2];
    float rgb0=0.f, rgb1=0.f, rgb2=0.f;

    for (int pt=0; pt<127; pt++){
        float dm = G[O_DM+pt];
        float t0=0.f, t1=0.f, t2=0.f;
        #pragma unroll
        for (int u=0; u<4; u++){
            float h = fmaxf(fmaf(dm, c1r[u], c0r[u]), 0.f);
            t0 = fmaf(h, rc0[u], t0);
            t1 = fmaf(h, rc1[u], t1);
            t2 = fmaf(h, rc2[u], t2);
        }
        #pragma unroll
        for (int o=16;o;o>>=1){
            t0 += __shfl_down_sync(0xffffffffu, t0, o);
            t1 += __shfl_down_sync(0xffffffffu, t1, o);
            t2 += __shfl_down_sync(0xffffffffu, t2, o);
        }
        if (lane == 0){
            float wv = G[O_WB+pt];
            rgb0 = fmaf(wv, sigf(t0+r2c0), rgb0);
            rgb1 = fmaf(wv, sigf(t1+r2c1), rgb1);
            rgb2 = fmaf(wv, sigf(t2+r2c2), rgb2);
        }
    }
    if (lane == 0){
        out[ray*5+0]=rgb0;
        out[ray*5+1]=rgb1;
        out[ray*5+2]=rgb2;
    }
}

extern "C" void kernel_launch(void* const* d_in, const int* in_sizes, int n_in,
                              void* d_out, int out_size)
{
    const float* rays_o = (const float*)d_in[0];
    const float* rays_d = (const float*)d_in[1];
    const float* W1 = (const float*)d_in[2];
    const float* b1 = (const float*)d_in[3];
    const float* W2 = (const float*)d_in[4];
    const float* b2 = (const float*)d_in[5];
    const float* W3 = (const float*)d_in[6];
    const float* b3 = (const float*)d_in[7];
    const float* R1 = (const float*)d_in[8];
    const float* r1 = (const float*)d_in[9];
    const float* R2 = (const float*)d_in[10];
    const float* r2 = (const float*)d_in[11];
    const float* sv = (const float*)d_in[12];
    float* out = (float*)d_out;

    cudaFuncSetAttribute(neus_kernel, cudaFuncAttributeMaxDynamicSharedMemorySize, SMEM_BYTES);
    neus_kernel<<<8192/RAYS, TPB, SMEM_BYTES>>>(rays_o,rays_d,W1,b1,W2,b2,W3,b3,R1,r1,R2,r2,sv,out);
}

// round 5
// speedup vs baseline: 2.3400x; 1.4327x over previous
#include <cuda_runtime.h>
#include <math.h>

#define TPB 512
#define RAYS 16
#define LDW2 132
#define HSTR 132
#define GSTRIDE 1760
#define W2T_FLOATS (128*LDW2)
#define WSOFF W2T_FLOATS
#define GOFF (W2T_FLOATS + 2056)
#define SMEM_BYTES ((GOFF + RAYS*GSTRIDE)*4)

#define O_D    0
#define O_SDF  128
#define O_H1   256
#define O_WB   1312
#define O_CDF  1440
#define O_DF   1572
#define O_SF   1588
#define O_DM   1604
#define O_AUX  1732

typedef unsigned long long ull;

__device__ __forceinline__ ull fma2(ull a, ull b, ull c){
    ull d;
    asm("fma.rn.f32x2 %0, %1, %2, %3;" : "=l"(d) : "l"(a), "l"(b), "l"(c));
    return d;
}
__device__ __forceinline__ float lo32(ull v){ return __uint_as_float((unsigned)v); }
__device__ __forceinline__ float hi32(ull v){ return __uint_as_float((unsigned)(v>>32)); }

__device__ __forceinline__ float sigf(float x){
    return 1.0f/(1.0f + __expf(-x));   // inf-safe: exp->inf => 0
}

// One 8-point SDF MLP batch for THIS warp's ray. Warp-private: only __syncwarp.
__device__ __forceinline__ void sdf_batch(
    float* __restrict__ G, const float* __restrict__ W2T,
    int din_off, int base, int sout_off, int lane,
    const float* c0, const float* c1, const float* b2v, const float* w3v,
    float b3v)
{
    float* gh1 = G + O_H1;
    #pragma unroll
    for (int pt=0; pt<8; pt++){
        float dv = G[din_off + base + pt];
        #pragma unroll
        for (int u=0; u<4; u++){
            gh1[pt*HSTR + lane + 32*u] = fmaxf(fmaf(dv, c1[u], c0[u]), 0.f);
        }
    }
    __syncwarp();

    ull acc[4][8];
    #pragma unroll
    for (int u=0; u<4; u++)
        #pragma unroll
        for (int p=0; p<8; p++)
            acc[u][p] = (ull)__float_as_uint(b2v[u]);

    const ulonglong2* w0 = (const ulonglong2*)(W2T + (lane      )*LDW2);
    const ulonglong2* w1 = (const ulonglong2*)(W2T + (lane + 32 )*LDW2);
    const ulonglong2* w2r= (const ulonglong2*)(W2T + (lane + 64 )*LDW2);
    const ulonglong2* w3r= (const ulonglong2*)(W2T + (lane + 96 )*LDW2);

    #pragma unroll 4
    for (int k4=0; k4<32; k4++){
        ulonglong2 wv[4];
        wv[0]=w0[k4]; wv[1]=w1[k4]; wv[2]=w2r[k4]; wv[3]=w3r[k4];
        #pragma unroll
        for (int hh=0; hh<2; hh++){
            ulonglong2 hv[4];
            #pragma unroll
            for (int i=0;i<4;i++)
                hv[i] = *(const ulonglong2*)(gh1 + (hh*4+i)*HSTR + k4*4);
            #pragma unroll
            for (int u=0; u<4; u++){
                #pragma unroll
                for (int i=0; i<4; i++){
                    int p = hh*4 + i;
                    acc[u][p] = fma2(wv[u].x, hv[i].x, acc[u][p]);
                    acc[u][p] = fma2(wv[u].y, hv[i].y, acc[u][p]);
                }
            }
        }
    }

    #pragma unroll
    for (int pt=0; pt<8; pt++){
        float t = 0.f;
        #pragma unroll
        for (int u=0; u<4; u++){
            float f = lo32(acc[u][pt]) + hi32(acc[u][pt]);
            t += fmaxf(f, 0.f) * w3v[u];
        }
        #pragma unroll
        for (int o=16;o;o>>=1) t += __shfl_down_sync(0xffffffffu, t, o);
        if (lane == 0) G[sout_off + base + pt] = t + b3v;
    }
    __syncwarp();
}

__global__ void __launch_bounds__(TPB,1) neus_kernel(
    const float* __restrict__ rays_o, const float* __restrict__ rays_d,
    const float* __restrict__ W1, const float* __restrict__ b1,
    const float* __restrict__ W2, const float* __restrict__ b2,
    const float* __restrict__ W3, const float* __restrict__ b3,
    const float* __restrict__ R1, const float* __restrict__ r1,
    const float* __restrict__ R2, const float* __restrict__ r2,
    const float* __restrict__ s_val, float* __restrict__ out)
{
    extern __shared__ float sm[];
    float* W2T = sm;
    float* WS  = sm + WSOFF;
    float* W1s = WS;         // 384
    float* b1s = WS+384;     // 128
    float* b2s = WS+512;     // 128
    float* W3s = WS+640;     // 128
    float* R1s = WS+768;     // 768
    float* r1s = WS+1536;    // 128
    float* R2s = WS+1664;    // 384
    float* r2s = WS+2048;    // 3
    float* b3p = WS+2051;
    float* scp = WS+2052;

    const int tid  = threadIdx.x;
    const int w    = tid >> 5;
    const int lane = tid & 31;
    const int ray  = blockIdx.x*RAYS + w;
    const unsigned FULL = 0xffffffffu;

    for (int idx=tid; idx<128*128; idx+=TPB){
        int k = idx >> 7, jj = idx & 127;
        W2T[jj*LDW2 + k] = W2[idx];
    }
    for (int idx=tid; idx<384; idx+=TPB) W1s[idx] = W1[idx];
    for (int idx=tid; idx<128; idx+=TPB){
        b1s[idx]=b1[idx]; b2s[idx]=b2[idx]; W3s[idx]=W3[idx]; r1s[idx]=r1[idx];
    }
    for (int idx=tid; idx<768; idx+=TPB) R1s[idx] = R1[idx];
    for (int idx=tid; idx<384; idx+=TPB) R2s[idx] = R2[idx];
    if (tid < 3) r2s[tid] = r2[tid];
    if (tid == 0){ b3p[0] = b3[0]; scp[0] = s_val[0]*64.0f; }
    __syncthreads();

    float* G = sm + GOFF + w*GSTRIDE;

    if (lane == 0){
        float ox=rays_o[ray*3+0], oy=rays_o[ray*3+1], oz=rays_o[ray*3+2];
        float ddx=rays_d[ray*3+0], ddy=rays_d[ray*3+1], ddz=rays_d[ray*3+2];
        float nrm = sqrtf(ddx*ddx+ddy*ddy+ddz*ddz);
        G[O_AUX+0]=ox; G[O_AUX+1]=oy; G[O_AUX+2]=oz;
        G[O_AUX+3]=ddx/nrm; G[O_AUX+4]=ddy/nrm; G[O_AUX+5]=ddz/nrm;
    }
    #pragma unroll
    for (int e=lane; e<64; e+=32){
        float t = (e==63) ? 1.0f : (float)e * (1.0f/63.0f);
        G[O_D + e] = 0.5f*(1.0f-t) + 4.0f*t;
    }
    __syncwarp();

    const float ox=G[O_AUX+0], oy=G[O_AUX+1], oz=G[O_AUX+2];
    const float dx=G[O_AUX+3], dy=G[O_AUX+4], dz=G[O_AUX+5];

    float c0[4], c1[4], b2v[4], w3v[4];
    #pragma unroll
    for (int u=0; u<4; u++){
        int j = lane + 32*u;
        c1[u] = dx*W1s[j] + dy*W1s[128+j] + dz*W1s[256+j];
        c0[u] = b1s[j] + ox*W1s[j] + oy*W1s[128+j] + oz*W1s[256+j];
        b2v[u]= b2s[j];
        w3v[u]= W3s[j];
    }
    const float b3v = b3p[0];

    // ---- coarse SDF ----
    for (int b=0;b<8;b++)
        sdf_batch(G, W2T, O_D, b*8, O_SDF, lane, c0,c1,b2v,w3v,b3v);

    // ---- hierarchical upsampling ----
    int n = 64;
    for (int it=0; it<4; it++){
        float s_i = 64.0f * (float)(1<<it);
        // alpha per interval (pad zeros to 128)
        #pragma unroll
        for (int e=lane; e<128; e+=32){
            float val = 0.0f;
            if (e < n-1){
                float psdf=G[O_SDF+e], nsdf=G[O_SDF+e+1], pz=G[O_D+e], nz=G[O_D+e+1];
                float dot = (nsdf-psdf)/(nz-pz+1e-5f);
                float pdot = 0.0f;
                if (e > 0){
                    float ppsdf=G[O_SDF+e-1], ppz=G[O_D+e-1];
                    pdot = (psdf-ppsdf)/(pz-ppz+1e-5f);
                }
                float dc = fminf(fmaxf(fminf(pdot,dot),-10.0f),0.0f);
                float mid = 0.5f*(psdf+nsdf), dist = nz-pz;
                float pc = sigf((mid - dc*dist*0.5f)*s_i);
                float nc = sigf((mid + dc*dist*0.5f)*s_i);
                val = (pc-nc+1e-5f)/(pc+1e-5f);
            }
            G[O_WB+e] = val;
        }
        __syncwarp();

        // warp scan: w = a*T + 1e-5 ; cdf = cumsum(w)/sum
        {
            float4 av = *(const float4*)(G + O_WB + 4*lane);
            float a[4] = {av.x, av.y, av.z, av.w};
            float sh[4], Tl[4], wv4[4];
            #pragma unroll
            for (int r=0;r<4;r++){
                int e = 4*lane + r;
                sh[r] = (e < n-1) ? (1.0f - a[r] + 1e-10f) : 1.0f;
            }
            Tl[0]=1.0f; Tl[1]=sh[0]; Tl[2]=sh[0]*sh[1]; Tl[3]=Tl[2]*sh[2];
            float P = Tl[3]*sh[3];
            // multiplicative exclusive scan of P
            float v = P;
            #pragma unroll
            for (int o=1;o<32;o<<=1){
                float t = __shfl_up_sync(FULL, v, o);
                if (lane >= o) v *= t;
            }
            float exc = __shfl_up_sync(FULL, v, 1);
            if (lane == 0) exc = 1.0f;
            float lsum = 0.f;
            #pragma unroll
            for (int r=0;r<4;r++){
                int e = 4*lane + r;
                wv4[r] = (e < n-1) ? fmaf(a[r], exc*Tl[r], 1e-5f) : 0.0f;
                lsum += wv4[r];
            }
            // additive scan of lane sums
            float va = lsum;
            #pragma unroll
            for (int o=1;o<32;o<<=1){
                float t = __shfl_up_sync(FULL, va, o);
                if (lane >= o) va += t;
            }
            float total = __shfl_sync(FULL, va, 31);
            float inv = 1.0f/total;
            float base = va - lsum;
            float run = 0.f;
            #pragma unroll
            for (int r=0;r<4;r++){
                run += wv4[r];
                G[O_CDF + 4*lane + 1 + r] = (base + run)*inv;
            }
            if (lane == 0) G[O_CDF] = 0.0f;
        }
        __syncwarp();

        // parallel searchsorted (side='right') + inverse-cdf sample
        if (lane < 16){
            float u = (lane==15) ? 1.0f : (float)lane * (1.0f/15.0f);
            int lo = 0, hi = n;
            #pragma unroll
            for (int s7=0; s7<7; s7++){
                int mid = (lo+hi) >> 1;
                if (G[O_CDF+mid] <= u) lo = mid+1; else hi = mid;
            }
            int ind = lo;
            int below = ind-1; if (below < 0) below = 0; if (below > n-1) below = n-1;
            int above = (ind < n-1) ? ind : n-1;
            float cb=G[O_CDF+below], ca=G[O_CDF+above];
            float bb=G[O_D+below],  ba=G[O_D+above];
            float den = ca-cb; if (den < 1e-5f) den = 1.0f;
            float tt = (u-cb)/den;
            G[O_DF+lane] = bb + tt*(ba-bb);
        }
        __syncwarp();

        sdf_batch(G, W2T, O_DF, 0, O_SF, lane, c0,c1,b2v,w3v,b3v);
        sdf_batch(G, W2T, O_DF, 8, O_SF, lane, c0,c1,b2v,w3v,b3v);

        // ---- parallel stable merge via ranks ----
        {
            float dv[4], sv[4]; int rk[4];
            #pragma unroll
            for (int m=0;m<4;m++){
                int e = lane + 32*m;
                rk[m] = -1;
                if (e < n){
                    dv[m]=G[O_D+e]; sv[m]=G[O_SDF+e];
                    int lo=0, hi=16;
                    #pragma unroll
                    for (int s5=0;s5<5;s5++){
                        int mid=(lo+hi)>>1;
                        if (mid < 16 && G[O_DF+mid] < dv[m]) lo=mid+1; else hi=mid;
                    }
                    rk[m] = e + lo;
                }
            }
            float bf=0.f, bsf=0.f; int rkf=-1;
            if (lane < 16){
                bf=G[O_DF+lane]; bsf=G[O_SF+lane];
                int lo=0, hi=n;
                #pragma unroll
                for (int s7=0;s7<7;s7++){
                    int mid=(lo+hi)>>1;
                    if (mid < n && G[O_D+mid] <= bf) lo=mid+1; else hi=mid;
                }
                rkf = lane + lo;
            }
            __syncwarp();
            #pragma unroll
            for (int m=0;m<4;m++){
                if (rk[m] >= 0){ G[O_D+rk[m]]=dv[m]; G[O_SDF+rk[m]]=sv[m]; }
            }
            if (rkf >= 0){ G[O_D+rkf]=bf; G[O_SDF+rkf]=bsf; }
        }
        __syncwarp();
        n += 16;
    }

    // ---- final compositing (n==128) ----
    const float s = scp[0];
    #pragma unroll
    for (int e=lane; e<128; e+=32) G[O_CDF+e] = sigf(G[O_SDF+e]*s);
    #pragma unroll
    for (int e=lane; e<128; e+=32) G[O_DM+e] = (e<127) ? 0.5f*(G[O_D+e]+G[O_D+e+1]) : 0.0f;
    __syncwarp();
    #pragma unroll
    for (int e=lane; e<128; e+=32){
        float val = 0.0f;
        if (e < 127){
            float a = (G[O_CDF+e]-G[O_CDF+e+1]+1e-5f)/(G[O_CDF+e]+1e-5f);
            val = fminf(fmaxf(a,0.0f),1.0f);
        }
        G[O_WB+e] = val;
    }
    __syncwarp();

    // vis_w scan (no epsilon), lane owns e = 4*lane + r
    float wv4[4], dm4[4];
    {
        float4 av = *(const float4*)(G + O_WB + 4*lane);
        float4 dmv= *(const float4*)(G + O_DM + 4*lane);
        float a[4] = {av.x, av.y, av.z, av.w};
        dm4[0]=dmv.x; dm4[1]=dmv.y; dm4[2]=dmv.z; dm4[3]=dmv.w;
        float sh[4], Tl[4];
        #pragma unroll
        for (int r=0;r<4;r++){
            int e = 4*lane + r;
            sh[r] = (e < 127) ? (1.0f - a[r] + 1e-10f) : 1.0f;
        }
        Tl[0]=1.0f; Tl[1]=sh[0]; Tl[2]=sh[0]*sh[1]; Tl[3]=Tl[2]*sh[2];
        float P = Tl[3]*sh[3];
        float v = P;
        #pragma unroll
        for (int o=1;o<32;o<<=1){
            float t = __shfl_up_sync(FULL, v, o);
            if (lane >= o) v *= t;
        }
        float exc = __shfl_up_sync(FULL, v, 1);
        if (lane == 0) exc = 1.0f;
        #pragma unroll
        for (int r=0;r<4;r++){
            int e = 4*lane + r;
            wv4[r] = (e < 127) ? a[r]*exc*Tl[r] : 0.0f;
        }
    }

    // ---- radiance: stage coefficients, flipped loop (lane owns 4 points) ----
    float* A0 = G + O_H1;         // c0r
    float* A1 = G + O_H1 + 128;   // c1r
    float* F0 = G + O_H1 + 256;   // rc0
    float* F1 = G + O_H1 + 384;   // rc1
    float* F2 = G + O_H1 + 512;   // rc2
    #pragma unroll
    for (int u=0; u<4; u++){
        int j = lane + 32*u;
        float c1r = dx*R1s[j] + dy*R1s[128+j] + dz*R1s[256+j];
        float c0r = r1s[j] + ox*R1s[j] + oy*R1s[128+j] + oz*R1s[256+j]
                  + dx*R1s[384+j] + dy*R1s[512+j] + dz*R1s[640+j];
        A0[j]=c0r; A1[j]=c1r;
        F0[j]=R2s[3*j+0]; F1[j]=R2s[3*j+1]; F2[j]=R2s[3*j+2];
    }
    __syncwarp();

    float t0[4]={0,0,0,0}, t1[4]={0,0,0,0}, t2[4]={0,0,0,0};
    #pragma unroll 2
    for (int k4=0; k4<32; k4++){
        float4 C0=*(const float4*)(A0+4*k4);
        float4 C1=*(const float4*)(A1+4*k4);
        float4 G0=*(const float4*)(F0+4*k4);
        float4 G1=*(const float4*)(F1+4*k4);
        float4 G2=*(const float4*)(F2+4*k4);
        const float c0k[4]={C0.x,C0.y,C0.z,C0.w};
        const float c1k[4]={C1.x,C1.y,C1.z,C1.w};
        const float f0k[4]={G0.x,G0.y,G0.z,G0.w};
        const float f1k[4]={G1.x,G1.y,G1.z,G1.w};
        const float f2k[4]={G2.x,G2.y,G2.z,G2.w};
        #pragma unroll
        for (int kk=0;kk<4;kk++){
            #pragma unroll
            for (int r=0;r<4;r++){
                float h = fmaxf(fmaf(dm4[r], c1k[kk], c0k[kk]), 0.f);
                t0[r] = fmaf(h, f0k[kk], t0[r]);
                t1[r] = fmaf(h, f1k[kk], t1[r]);
                t2[r] = fmaf(h, f2k[kk], t2[r]);
            }
        }
    }

    const float r2c0=r2s[0], r2c1=r2s[1], r2c2=r2s[2];
    float rgb0=0.f, rgb1=0.f, rgb2=0.f, dep=0.f, ac=0.f;
    #pragma unroll
    for (int r=0;r<4;r++){
        float wvv = wv4[r];
        rgb0 = fmaf(wvv, sigf(t0[r]+r2c0), rgb0);
        rgb1 = fmaf(wvv, sigf(t1[r]+r2c1), rgb1);
        rgb2 = fmaf(wvv, sigf(t2[r]+r2c2), rgb2);
        dep  = fmaf(wvv, dm4[r], dep);
        ac  += wvv;
    }
    #pragma unroll
    for (int o=16;o;o>>=1){
        rgb0 += __shfl_down_sync(FULL, rgb0, o);
        rgb1 += __shfl_down_sync(FULL, rgb1, o);
        rgb2 += __shfl_down_sync(FULL, rgb2, o);
        dep  += __shfl_down_sync(FULL, dep, o);
        ac   += __shfl_down_sync(FULL, ac, o);
    }
    if (lane == 0){
        out[ray*5+0]=rgb0;
        out[ray*5+1]=rgb1;
        out[ray*5+2]=rgb2;
        out[ray*5+3]=dep;
        out[ray*5+4]=ac;
    }
}

extern "C" void kernel_launch(void* const* d_in, const int* in_sizes, int n_in,
                              void* d_out, int out_size)
{
    const float* rays_o = (const float*)d_in[0];
    const float* rays_d = (const float*)d_in[1];
    const float* W1 = (const float*)d_in[2];
    const float* b1 = (const float*)d_in[3];
    const float* W2 = (const float*)d_in[4];
    const float* b2 = (const float*)d_in[5];
    const float* W3 = (const float*)d_in[6];
    const float* b3 = (const float*)d_in[7];
    const float* R1 = (const float*)d_in[8];
    const float* r1 = (const float*)d_in[9];
    const float* R2 = (const float*)d_in[10];
    const float* r2 = (const float*)d_in[11];
    const float* sv = (const float*)d_in[12];
    float* out = (float*)d_out;

    cudaFuncSetAttribute(neus_kernel, cudaFuncAttributeMaxDynamicSharedMemorySize, SMEM_BYTES);
    neus_kernel<<<8192/RAYS, TPB, SMEM_BYTES>>>(rays_o,rays_d,W1,b1,W2,b2,W3,b3,R1,r1,R2,r2,sv,out);
}